// round 5
// baseline (speedup 1.0000x reference)
#include <cuda_runtime.h>

#define GN 4096   // N*N
#define TT 168    // T
#define BB 128    // B
#define NN 64     // N
#define PP 128    // P

#define ROWS_PER_BLK 8
#define MV_BLOCKS (GN / ROWS_PER_BLK)      // 512
#define TOTAL_BLK (MV_BLOCKS + BB)         // 640

// Scratch + sync (allocation-free rule: __device__ globals)
__device__ float d_v[GN];
__device__ int   d_mv_done;   // zero-initialized at module load; self-resetting
__device__ int   d_z_done;

__device__ __forceinline__ float dot4(float4 a, float4 b) {
    return a.x * b.x + a.y * b.y + a.z * b.z + a.w * b.w;
}

// ---------------------------------------------------------------------------
// Single fused kernel.
//  blocks [0, 512):   matvec, 8 rows/block, warp-per-row, w^2 staged in smem.
//                     Fused F epilogue. Then fence + signal d_mv_done.
//  blocks [512, 640): per-batch y[b,j] = sum_p x[b,j,p]*alpha[x_i[b,p]]
//                     (DRAM traffic overlaps matvec L2 traffic), then spin
//                     until d_mv_done==512, stage v, compute Z[b,:] in-place.
// Deadlock-free: spinners never gate matvec blocks; matvec blocks always
// make progress, so pending blocks always get scheduled.
// Counters reset by the last Z block -> identical state every graph replay.
// ---------------------------------------------------------------------------
__global__ void __launch_bounds__(256) k_fused(const float* __restrict__ g,
                                               const float* __restrict__ w,
                                               const float* __restrict__ alphas,
                                               const float* __restrict__ x,
                                               const int*   __restrict__ xi,
                                               float* __restrict__ Fout,
                                               float* __restrict__ Zout) {
    // pool: matvec -> w^2 (4096 floats); y/Z-block -> padded v (64*65=4160)
    __shared__ __align__(16) float pool[NN * 65];
    __shared__ float sal[TT];
    __shared__ float ap[PP];
    __shared__ float yv[NN];

    const int blk  = blockIdx.x;
    const int tid  = threadIdx.x;
    const int wid  = tid >> 5;
    const int lane = tid & 31;

    if (blk < MV_BLOCKS) {
        // ---- stage w^2 (16 KB) + alphas into smem ----
        const float4* __restrict__ w4g = reinterpret_cast<const float4*>(w);
        float4* ws4 = reinterpret_cast<float4*>(pool);
        #pragma unroll
        for (int k = 0; k < 4; k++) {
            float4 t = w4g[tid + k * 256];
            t.x *= t.x; t.y *= t.y; t.z *= t.z; t.w *= t.w;
            ws4[tid + k * 256] = t;
        }
        if (tid < TT) sal[tid] = alphas[tid];
        __syncthreads();

        // ---- warp-per-row dot product ----
        const int row = blk * ROWS_PER_BLK + wid;
        const float4* __restrict__ g4 =
            reinterpret_cast<const float4*>(g + (size_t)row * GN);

        float acc0 = 0.f, acc1 = 0.f, acc2 = 0.f, acc3 = 0.f;
        #pragma unroll
        for (int c = 0; c < 8; c++) {
            const int base = c * 128 + lane;          // float4 units
            float4 a0 = g4[base];       float4 a1 = g4[base + 32];
            float4 a2 = g4[base + 64];  float4 a3 = g4[base + 96];
            float4 b0 = ws4[base];      float4 b1 = ws4[base + 32];
            float4 b2 = ws4[base + 64]; float4 b3 = ws4[base + 96];
            acc0 += dot4(a0, b0);
            acc1 += dot4(a1, b1);
            acc2 += dot4(a2, b2);
            acc3 += dot4(a3, b3);
        }
        float s = (acc0 + acc1) + (acc2 + acc3);
        #pragma unroll
        for (int o = 16; o > 0; o >>= 1)
            s += __shfl_xor_sync(0xffffffffu, s, o);   // all lanes get sum

        if (lane == 0) d_v[row] = s;

        // ---- F epilogue ----
        float* __restrict__ Frow = Fout + (size_t)row * TT;
        #pragma unroll
        for (int t = lane; t < TT; t += 32)
            Frow[t] = s * sal[t];

        // ---- publish: make d_v visible, then signal ----
        if (lane == 0) __threadfence();
        __syncthreads();
        if (tid == 0) atomicAdd(&d_mv_done, 1);
    } else {
        // ---- y-block for batch b ----
        const int b = blk - MV_BLOCKS;
        if (tid < PP)
            ap[tid] = alphas[xi[b * PP + tid]];
        __syncthreads();

        #pragma unroll
        for (int j = wid; j < NN; j += 8) {
            const float* __restrict__ xr = x + ((size_t)b * NN + j) * PP;
            float s = xr[lane]      * ap[lane]
                    + xr[lane + 32] * ap[lane + 32]
                    + xr[lane + 64] * ap[lane + 64]
                    + xr[lane + 96] * ap[lane + 96];
            #pragma unroll
            for (int o = 16; o > 0; o >>= 1)
                s += __shfl_xor_sync(0xffffffffu, s, o);
            if (lane == 0) yv[j] = s;
        }
        __syncthreads();

        // ---- gate: wait for all matvec blocks ----
        if (tid == 0) {
            while (atomicAdd(&d_mv_done, 0) < MV_BLOCKS)
                __nanosleep(64);
            __threadfence();
        }
        __syncthreads();

        // ---- stage v (L2, bypass L1) into padded smem, MLP=16 ----
        #pragma unroll
        for (int k = 0; k < 16; k++) {
            int i = tid + k * 256;
            pool[(i >> 6) * 65 + (i & 63)] = __ldcg(&d_v[i]);
        }
        __syncthreads();

        // ---- Z[b,i] = sum_j v[i*64+j] * y[b,j] ----
        if (tid < NN) {
            float s = 0.f;
            #pragma unroll
            for (int j = 0; j < NN; j++)
                s += pool[tid * 65 + j] * yv[j];
            Zout[b * NN + tid] = s;
        }
        __syncthreads();

        // ---- last Z block resets counters for the next graph replay ----
        if (tid == 0) {
            if (atomicAdd(&d_z_done, 1) == BB - 1) {
                atomicExch(&d_z_done, 0);
                atomicExch(&d_mv_done, 0);
            }
        }
    }
}

// ---------------------------------------------------------------------------
extern "C" void kernel_launch(void* const* d_in, const int* in_sizes, int n_in,
                              void* d_out, int out_size) {
    const float* x      = (const float*)d_in[0];   // [B, N, P]
    const int*   xi     = (const int*)  d_in[1];   // [B, P]
    const float* g      = (const float*)d_in[2];   // [N*N, N*N]
    const float* w      = (const float*)d_in[3];   // [N*N, 1]
    const float* alphas = (const float*)d_in[4];   // [1, T]

    float* out = (float*)d_out;
    float* Z = out;               // [B, N]   = 8192
    float* F = out + BB * NN;     // [N*N, T] = 688128

    k_fused<<<TOTAL_BLK, 256>>>(g, w, alphas, x, xi, F, Z);
}

// round 6
// speedup vs baseline: 1.0311x; 1.0311x over previous
#include <cuda_runtime.h>

#define GN 4096   // N*N
#define TT 168    // T
#define BB 128    // B
#define NN 64     // N
#define PP 128    // P

#define ROWS_PER_BLK 8
#define MV_BLOCKS (GN / ROWS_PER_BLK)      // 512
#define TOTAL_BLK (BB + MV_BLOCKS)         // 128 y-blocks first, then 512 matvec

// Scratch + sync (allocation-free rule: __device__ globals)
__device__ float d_yt[NN * BB];   // y transposed: y_t[j*BB + b]
__device__ int   d_y_done;        // zero at load; self-resetting each replay
__device__ int   d_mv_done;

__device__ __forceinline__ float dot4(float4 a, float4 b) {
    return a.x * b.x + a.y * b.y + a.z * b.z + a.w * b.w;
}

// ---------------------------------------------------------------------------
// Single fused kernel, dependency-inverted (no tail):
//  blocks [0, 128):   y-block for batch b: ap[p]=alpha[xi[b,p]],
//                     y_t[j][b] = sum_p x[b,j,p]*ap[p]; zero Z[b,:];
//                     fence; signal d_y_done.  (DRAM-bound, done in ~2us)
//  blocks [128, 640): matvec m: 8 rows r=8m..8m+7 (all same i=m>>3,
//                     j = 8*(m&7)+k). w^2 staged in smem, warp-per-row dot
//                     from L2. Fused F epilogue. Then (y long since ready)
//                     scatter Z[b,i] += sum_k v_k * y_t[j0+k][b] via
//                     atomicAdd — spread addresses, REDG-fast.
// Deadlock-free: y-blocks are first in issue order (wave-1 resident);
// matvec blocks only wait after finishing their dot, by which time y is done.
// Counters reset by last matvec block -> identical state every replay.
// ---------------------------------------------------------------------------
__global__ void __launch_bounds__(256) k_fused(const float* __restrict__ g,
                                               const float* __restrict__ w,
                                               const float* __restrict__ alphas,
                                               const float* __restrict__ x,
                                               const int*   __restrict__ xi,
                                               float* __restrict__ Fout,
                                               float* __restrict__ Zout) {
    __shared__ __align__(16) float ws[GN];   // matvec: w^2 | y-block: ap reuse
    __shared__ float sal[TT];
    __shared__ float vsh[ROWS_PER_BLK];

    const int blk  = blockIdx.x;
    const int tid  = threadIdx.x;
    const int wid  = tid >> 5;
    const int lane = tid & 31;

    if (blk < BB) {
        // ---------------- y-block for batch b ----------------
        const int b = blk;
        float* ap = ws;
        if (tid < PP)
            ap[tid] = alphas[xi[b * PP + tid]];
        // zero this batch's Z slice (d_out is poisoned)
        if (tid >= 128 && tid < 128 + NN)
            Zout[b * NN + (tid - 128)] = 0.f;
        __syncthreads();

        #pragma unroll
        for (int j = wid; j < NN; j += 8) {
            const float* __restrict__ xr = x + ((size_t)b * NN + j) * PP;
            float s = xr[lane]      * ap[lane]
                    + xr[lane + 32] * ap[lane + 32]
                    + xr[lane + 64] * ap[lane + 64]
                    + xr[lane + 96] * ap[lane + 96];
            #pragma unroll
            for (int o = 16; o > 0; o >>= 1)
                s += __shfl_xor_sync(0xffffffffu, s, o);
            if (lane == 0) d_yt[j * BB + b] = s;
        }
        __syncthreads();
        if (tid == 0) {
            __threadfence();
            atomicAdd(&d_y_done, 1);
        }
    } else {
        // ---------------- matvec block m ----------------
        const int m = blk - BB;

        // stage w^2 (16 KB) + alphas into smem
        const float4* __restrict__ w4g = reinterpret_cast<const float4*>(w);
        float4* ws4 = reinterpret_cast<float4*>(ws);
        #pragma unroll
        for (int k = 0; k < 4; k++) {
            float4 t = w4g[tid + k * 256];
            t.x *= t.x; t.y *= t.y; t.z *= t.z; t.w *= t.w;
            ws4[tid + k * 256] = t;
        }
        if (tid < TT) sal[tid] = alphas[tid];
        __syncthreads();

        // warp-per-row dot product (row = 8m + wid)
        const int row = m * ROWS_PER_BLK + wid;
        const float4* __restrict__ g4 =
            reinterpret_cast<const float4*>(g + (size_t)row * GN);

        float acc0 = 0.f, acc1 = 0.f, acc2 = 0.f, acc3 = 0.f;
        #pragma unroll
        for (int c = 0; c < 8; c++) {
            const int base = c * 128 + lane;          // float4 units
            float4 a0 = g4[base];       float4 a1 = g4[base + 32];
            float4 a2 = g4[base + 64];  float4 a3 = g4[base + 96];
            float4 b0 = ws4[base];      float4 b1 = ws4[base + 32];
            float4 b2 = ws4[base + 64]; float4 b3 = ws4[base + 96];
            acc0 += dot4(a0, b0);
            acc1 += dot4(a1, b1);
            acc2 += dot4(a2, b2);
            acc3 += dot4(a3, b3);
        }
        float s = (acc0 + acc1) + (acc2 + acc3);
        #pragma unroll
        for (int o = 16; o > 0; o >>= 1)
            s += __shfl_xor_sync(0xffffffffu, s, o);   // all lanes get sum

        // F epilogue: F[row, t] = v * alpha[t]
        float* __restrict__ Frow = Fout + (size_t)row * TT;
        #pragma unroll
        for (int t = lane; t < TT; t += 32)
            Frow[t] = s * sal[t];

        if (lane == 0) vsh[wid] = s;

        // gate on y (already done ~always; acquire ordering via fence)
        __syncthreads();
        if (tid == 0) {
            while (atomicAdd(&d_y_done, 0) < BB)
                __nanosleep(32);
            __threadfence();
        }
        __syncthreads();

        // scatter Z contribution: i = m>>3, j0 = 8*(m&7)
        // thread t = batch b (t < 128): c = sum_k vsh[k] * y_t[j0+k][b]
        if (tid < BB) {
            const int i  = m >> 3;
            const int j0 = (m & 7) * ROWS_PER_BLK;
            const float* __restrict__ yt = d_yt + j0 * BB + tid;
            float c = vsh[0] * yt[0]
                    + vsh[1] * yt[BB]
                    + vsh[2] * yt[2 * BB]
                    + vsh[3] * yt[3 * BB]
                    + vsh[4] * yt[4 * BB]
                    + vsh[5] * yt[5 * BB]
                    + vsh[6] * yt[6 * BB]
                    + vsh[7] * yt[7 * BB];
            atomicAdd(&Zout[tid * NN + i], c);
        }
        __syncthreads();

        // last matvec block resets counters for next graph replay
        if (tid == 0) {
            if (atomicAdd(&d_mv_done, 1) == MV_BLOCKS - 1) {
                atomicExch(&d_mv_done, 0);
                atomicExch(&d_y_done, 0);
            }
        }
    }
}

// ---------------------------------------------------------------------------
extern "C" void kernel_launch(void* const* d_in, const int* in_sizes, int n_in,
                              void* d_out, int out_size) {
    const float* x      = (const float*)d_in[0];   // [B, N, P]
    const int*   xi     = (const int*)  d_in[1];   // [B, P]
    const float* g      = (const float*)d_in[2];   // [N*N, N*N]
    const float* w      = (const float*)d_in[3];   // [N*N, 1]
    const float* alphas = (const float*)d_in[4];   // [1, T]

    float* out = (float*)d_out;
    float* Z = out;               // [B, N]   = 8192
    float* F = out + BB * NN;     // [N*N, T] = 688128

    k_fused<<<TOTAL_BLK, 256>>>(g, w, alphas, x, xi, F, Z);
}

// round 7
// speedup vs baseline: 1.1373x; 1.1029x over previous
#include <cuda_runtime.h>

#define GN 4096   // N*N
#define TT 168    // T
#define BB 128    // B
#define NN 64     // N
#define PP 128    // P

#define ROWS_PER_BLK 8
#define MV_BLOCKS (GN / ROWS_PER_BLK)      // 512
#define TOTAL_K1  (MV_BLOCKS + BB)         // 640

// Scratch (allocation-free rule: __device__ globals)
__device__ float d_v[GN];
__device__ float d_y[BB * NN];

__device__ __forceinline__ float dot4(float4 a, float4 b) {
    return a.x * b.x + a.y * b.y + a.z * b.z + a.w * b.w;
}

// ---------------------------------------------------------------------------
// Kernel 1 (unchanged from Round 4 — proven ~7.8us, near LTS floor):
//  blocks [0, 512):  matvec, 8 rows/block, warp-per-row, w^2 staged in smem
//                    once per block. Fused F epilogue.
//  blocks [512, 640): per-batch y[b,j] = sum_p x[b,j,p]*alpha[x_i[b,p]]
//                    (4 MB DRAM traffic overlaps matvec L2 traffic).
// No cross-block sync, no atomics.
// ---------------------------------------------------------------------------
__global__ void __launch_bounds__(256) k_main(const float* __restrict__ g,
                                              const float* __restrict__ w,
                                              const float* __restrict__ alphas,
                                              const float* __restrict__ x,
                                              const int*   __restrict__ xi,
                                              float* __restrict__ Fout) {
    __shared__ __align__(16) float ws[GN];   // matvec: w^2 | y-block: ap reuse
    __shared__ float sal[TT];

    const int blk  = blockIdx.x;
    const int tid  = threadIdx.x;
    const int wid  = tid >> 5;
    const int lane = tid & 31;

    if (blk < MV_BLOCKS) {
        // ---- stage w^2 (16 KB) + alphas into smem ----
        const float4* __restrict__ w4g = reinterpret_cast<const float4*>(w);
        float4* ws4 = reinterpret_cast<float4*>(ws);
        #pragma unroll
        for (int k = 0; k < 4; k++) {
            float4 t = w4g[tid + k * 256];
            t.x *= t.x; t.y *= t.y; t.z *= t.z; t.w *= t.w;
            ws4[tid + k * 256] = t;
        }
        if (tid < TT) sal[tid] = alphas[tid];
        __syncthreads();

        // ---- warp-per-row dot product ----
        const int row = blk * ROWS_PER_BLK + wid;
        const float4* __restrict__ g4 =
            reinterpret_cast<const float4*>(g + (size_t)row * GN);

        float acc0 = 0.f, acc1 = 0.f, acc2 = 0.f, acc3 = 0.f;
        #pragma unroll
        for (int c = 0; c < 8; c++) {
            const int base = c * 128 + lane;          // float4 units
            float4 a0 = g4[base];       float4 a1 = g4[base + 32];
            float4 a2 = g4[base + 64];  float4 a3 = g4[base + 96];
            float4 b0 = ws4[base];      float4 b1 = ws4[base + 32];
            float4 b2 = ws4[base + 64]; float4 b3 = ws4[base + 96];
            acc0 += dot4(a0, b0);
            acc1 += dot4(a1, b1);
            acc2 += dot4(a2, b2);
            acc3 += dot4(a3, b3);
        }
        float s = (acc0 + acc1) + (acc2 + acc3);
        #pragma unroll
        for (int o = 16; o > 0; o >>= 1)
            s += __shfl_xor_sync(0xffffffffu, s, o);   // all lanes get sum

        if (lane == 0) d_v[row] = s;

        // ---- F epilogue: F[row, t] = v * alpha[t] ----
        float* __restrict__ Frow = Fout + (size_t)row * TT;
        #pragma unroll
        for (int t = lane; t < TT; t += 32)
            Frow[t] = s * sal[t];
    } else {
        // ---- y-block: batch b ----
        const int b = blk - MV_BLOCKS;
        float* ap = ws;   // reuse smem
        if (tid < PP)
            ap[tid] = alphas[xi[b * PP + tid]];
        __syncthreads();

        #pragma unroll
        for (int j = wid; j < NN; j += 8) {
            const float* __restrict__ xr = x + ((size_t)b * NN + j) * PP;
            float s = xr[lane]      * ap[lane]
                    + xr[lane + 32] * ap[lane + 32]
                    + xr[lane + 64] * ap[lane + 64]
                    + xr[lane + 96] * ap[lane + 96];
            #pragma unroll
            for (int o = 16; o > 0; o >>= 1)
                s += __shfl_xor_sync(0xffffffffu, s, o);
            if (lane == 0) d_y[b * NN + j] = s;
        }
    }
}

// ---------------------------------------------------------------------------
// Kernel 2: Z[b,i] = sum_j v[i*64+j] * y[b,j]
// grid 128 (one block per batch, every SM busy), 256 threads.
// One output per 4-thread quad: thread (i = tid>>2, q = tid&3) loads 4
// consecutive float4 of v row i (64 B, coalesced, 4 loads in flight) and
// dots against y[q*16..q*16+15] from smem; 2 shfl_xor reduce the quad.
// Critical path ~ 2 L2 round trips — no long serial stage, no big smem.
// ---------------------------------------------------------------------------
__global__ void __launch_bounds__(256) k_z(float* __restrict__ Zout) {
    const int b   = blockIdx.x;
    const int tid = threadIdx.x;
    __shared__ __align__(16) float sy[NN];

    if (tid < NN) sy[tid] = d_y[b * NN + tid];
    __syncthreads();

    const int i = tid >> 2;        // output row 0..63
    const int q = tid & 3;         // j-segment 0..3 (16 j's each)

    const float4* __restrict__ v4 =
        reinterpret_cast<const float4*>(d_v) + i * 16 + q * 4;
    const float4* __restrict__ y4 =
        reinterpret_cast<const float4*>(sy) + q * 4;

    float4 a0 = v4[0]; float4 a1 = v4[1]; float4 a2 = v4[2]; float4 a3 = v4[3];
    float4 b0 = y4[0]; float4 b1 = y4[1]; float4 b2 = y4[2]; float4 b3 = y4[3];

    float s = (dot4(a0, b0) + dot4(a1, b1)) + (dot4(a2, b2) + dot4(a3, b3));
    s += __shfl_xor_sync(0xffffffffu, s, 1);
    s += __shfl_xor_sync(0xffffffffu, s, 2);

    if (q == 0)
        Zout[b * NN + i] = s;
}

// ---------------------------------------------------------------------------
extern "C" void kernel_launch(void* const* d_in, const int* in_sizes, int n_in,
                              void* d_out, int out_size) {
    const float* x      = (const float*)d_in[0];   // [B, N, P]
    const int*   xi     = (const int*)  d_in[1];   // [B, P]
    const float* g      = (const float*)d_in[2];   // [N*N, N*N]
    const float* w      = (const float*)d_in[3];   // [N*N, 1]
    const float* alphas = (const float*)d_in[4];   // [1, T]

    float* out = (float*)d_out;
    float* Z = out;               // [B, N]   = 8192
    float* F = out + BB * NN;     // [N*N, T] = 688128

    k_main<<<TOTAL_K1, 256>>>(g, w, alphas, x, xi, F);
    k_z<<<BB, 256>>>(Z);
}

// round 8
// speedup vs baseline: 1.1400x; 1.0025x over previous
#include <cuda_runtime.h>

#define GN 4096   // N*N
#define TT 168    // T
#define BB 128    // B
#define NN 64     // N
#define PP 128    // P

#define ROWS_PER_BLK 8
#define MV_BLOCKS (GN / ROWS_PER_BLK)      // 512
#define TOTAL_K1  (MV_BLOCKS + BB)         // 640

// Scratch (allocation-free rule: __device__ globals)
__device__ float d_v[GN];
__device__ float d_y[BB * NN];

__device__ __forceinline__ float dot4(float4 a, float4 b) {
    return a.x * b.x + a.y * b.y + a.z * b.z + a.w * b.w;
}

// ---------------------------------------------------------------------------
// Kernel 1 (hot path unchanged — proven ~7.8us, near LTS floor):
//  blocks [0, 512):  matvec, 8 rows/block, warp-per-row, w^2 staged in smem.
//                    Fused F epilogue.
//  blocks [512, 640): per-batch y[b,j] = sum_p x[b,j,p]*alpha[x_i[b,p]].
// Each block fences its global writes then triggers PDL so k_z's
// GridDependencySynchronize releases at data-ready time.
// ---------------------------------------------------------------------------
__global__ void __launch_bounds__(256) k_main(const float* __restrict__ g,
                                              const float* __restrict__ w,
                                              const float* __restrict__ alphas,
                                              const float* __restrict__ x,
                                              const int*   __restrict__ xi,
                                              float* __restrict__ Fout) {
    __shared__ __align__(16) float ws[GN];   // matvec: w^2 | y-block: ap reuse
    __shared__ float sal[TT];

    const int blk  = blockIdx.x;
    const int tid  = threadIdx.x;
    const int wid  = tid >> 5;
    const int lane = tid & 31;

    if (blk < MV_BLOCKS) {
        // ---- stage w^2 (16 KB) + alphas into smem ----
        const float4* __restrict__ w4g = reinterpret_cast<const float4*>(w);
        float4* ws4 = reinterpret_cast<float4*>(ws);
        #pragma unroll
        for (int k = 0; k < 4; k++) {
            float4 t = w4g[tid + k * 256];
            t.x *= t.x; t.y *= t.y; t.z *= t.z; t.w *= t.w;
            ws4[tid + k * 256] = t;
        }
        if (tid < TT) sal[tid] = alphas[tid];
        __syncthreads();

        // ---- warp-per-row dot product ----
        const int row = blk * ROWS_PER_BLK + wid;
        const float4* __restrict__ g4 =
            reinterpret_cast<const float4*>(g + (size_t)row * GN);

        float acc0 = 0.f, acc1 = 0.f, acc2 = 0.f, acc3 = 0.f;
        #pragma unroll
        for (int c = 0; c < 8; c++) {
            const int base = c * 128 + lane;          // float4 units
            float4 a0 = g4[base];       float4 a1 = g4[base + 32];
            float4 a2 = g4[base + 64];  float4 a3 = g4[base + 96];
            float4 b0 = ws4[base];      float4 b1 = ws4[base + 32];
            float4 b2 = ws4[base + 64]; float4 b3 = ws4[base + 96];
            acc0 += dot4(a0, b0);
            acc1 += dot4(a1, b1);
            acc2 += dot4(a2, b2);
            acc3 += dot4(a3, b3);
        }
        float s = (acc0 + acc1) + (acc2 + acc3);
        #pragma unroll
        for (int o = 16; o > 0; o >>= 1)
            s += __shfl_xor_sync(0xffffffffu, s, o);   // all lanes get sum

        if (lane == 0) d_v[row] = s;

        // ---- F epilogue: F[row, t] = v * alpha[t] ----
        float* __restrict__ Frow = Fout + (size_t)row * TT;
        #pragma unroll
        for (int t = lane; t < TT; t += 32)
            Frow[t] = s * sal[t];
    } else {
        // ---- y-block: batch b ----
        const int b = blk - MV_BLOCKS;
        float* ap = ws;   // reuse smem
        if (tid < PP)
            ap[tid] = alphas[xi[b * PP + tid]];
        __syncthreads();

        #pragma unroll
        for (int j = wid; j < NN; j += 8) {
            const float* __restrict__ xr = x + ((size_t)b * NN + j) * PP;
            float s = xr[lane]      * ap[lane]
                    + xr[lane + 32] * ap[lane + 32]
                    + xr[lane + 64] * ap[lane + 64]
                    + xr[lane + 96] * ap[lane + 96];
            #pragma unroll
            for (int o = 16; o > 0; o >>= 1)
                s += __shfl_xor_sync(0xffffffffu, s, o);
            if (lane == 0) d_y[b * NN + j] = s;
        }
    }

    // ---- publish writes, then allow dependent kernel to proceed ----
    __threadfence();
    cudaTriggerProgrammaticLaunchCompletion();
}

// ---------------------------------------------------------------------------
// Kernel 2 (PDL secondary): Z[b,i] = sum_j v[i*64+j] * y[b,j]
// Launched programmatically: blocks schedule + ramp while k_main runs;
// GridDependencySynchronize gates only the data reads.
// One output per 4-thread quad; all 8 float4 loads issued back-to-back
// (single L2 round-trip critical path), no smem, no __syncthreads.
// ---------------------------------------------------------------------------
__global__ void __launch_bounds__(256) k_z(float* __restrict__ Zout) {
    const int b   = blockIdx.x;
    const int tid = threadIdx.x;
    const int i   = tid >> 2;      // output row 0..63
    const int q   = tid & 3;       // j-segment 0..3 (16 j's each)

    cudaGridDependencySynchronize();

    const float4* __restrict__ v4 =
        reinterpret_cast<const float4*>(d_v) + i * 16 + q * 4;
    const float4* __restrict__ y4 =
        reinterpret_cast<const float4*>(d_y) + b * 16 + q * 4;

    float4 a0 = v4[0]; float4 a1 = v4[1]; float4 a2 = v4[2]; float4 a3 = v4[3];
    float4 b0 = y4[0]; float4 b1 = y4[1]; float4 b2 = y4[2]; float4 b3 = y4[3];

    float s = (dot4(a0, b0) + dot4(a1, b1)) + (dot4(a2, b2) + dot4(a3, b3));
    s += __shfl_xor_sync(0xffffffffu, s, 1);
    s += __shfl_xor_sync(0xffffffffu, s, 2);

    if (q == 0)
        Zout[b * NN + i] = s;
}

// ---------------------------------------------------------------------------
extern "C" void kernel_launch(void* const* d_in, const int* in_sizes, int n_in,
                              void* d_out, int out_size) {
    const float* x      = (const float*)d_in[0];   // [B, N, P]
    const int*   xi     = (const int*)  d_in[1];   // [B, P]
    const float* g      = (const float*)d_in[2];   // [N*N, N*N]
    const float* w      = (const float*)d_in[3];   // [N*N, 1]
    const float* alphas = (const float*)d_in[4];   // [1, T]

    float* out = (float*)d_out;
    float* Z = out;               // [B, N]   = 8192
    float* F = out + BB * NN;     // [N*N, T] = 688128

    k_main<<<TOTAL_K1, 256>>>(g, w, alphas, x, xi, F);

    // PDL launch of k_z: overlaps its launch/ramp with k_main execution.
    cudaLaunchConfig_t cfg = {};
    cfg.gridDim  = dim3(BB, 1, 1);
    cfg.blockDim = dim3(256, 1, 1);
    cfg.dynamicSmemBytes = 0;
    cfg.stream = 0;
    cudaLaunchAttribute attr[1];
    attr[0].id = cudaLaunchAttributeProgrammaticStreamSerialization;
    attr[0].val.programmaticStreamSerializationAllowed = 1;
    cfg.attrs = attr;
    cfg.numAttrs = 1;
    cudaLaunchKernelEx(&cfg, k_z, Z);
}